// round 6
// baseline (speedup 1.0000x reference)
#include <cuda_runtime.h>
#include <stdint.h>

#define BATCH   4
#define NPTS    100000
#define TOTAL   (BATCH * NPTS)
#define D_IN    16
#define D_TOT   19
#define MLP_N   128
#define GRID_X  468
#define GRID_Y  468
#define VOL     (GRID_X * GRID_Y)
#define NVOX    (BATCH * VOL)        // 876096
#define CAP     16                   // λ≈0.19/voxel → P(count>16) astronomically small

#define FILL_THREADS 256
#define FILL_BLOCKS  296             // persistent: 2 blocks/SM

// Scratch (__device__ globals — no allocation allowed)
__device__ int d_cnt[NVOX];                 // per-voxel point count
__device__ int d_pidx[(size_t)NVOX * CAP];  // per-voxel point indices
__device__ int d_occ[NVOX];                 // compacted occupied-voxel ids
__device__ int d_nocc;                      // occupied count

// ---- packed f32x2 helpers (FFMA2 path, PTX-only) ----
__device__ __forceinline__ unsigned long long pack2(float lo, float hi) {
    unsigned long long r;
    asm("mov.b64 %0, {%1, %2};" : "=l"(r) : "f"(lo), "f"(hi));
    return r;
}
__device__ __forceinline__ unsigned long long dup2(float v) {
    unsigned long long r;
    asm("mov.b64 %0, {%1, %1};" : "=l"(r) : "f"(v));
    return r;
}
__device__ __forceinline__ unsigned long long fma2(unsigned long long a,
                                                   unsigned long long b,
                                                   unsigned long long c) {
    unsigned long long d;
    asm("fma.rn.f32x2 %0, %1, %2, %3;" : "=l"(d) : "l"(a), "l"(b), "l"(c));
    return d;
}
__device__ __forceinline__ void unpack2(unsigned long long p, float& lo, float& hi) {
    asm("mov.b64 {%0, %1}, %2;" : "=f"(lo), "=f"(hi) : "l"(p));
}

// ---- K1: zero counters + list head ----
__global__ void zero_cnt_kernel() {
    const int i = blockIdx.x * blockDim.x + threadIdx.x;
    if (i == 0) d_nocc = 0;
    int4* p = (int4*)d_cnt;
    if (i < NVOX / 4) p[i] = make_int4(0, 0, 0, 0);
}

// ---- K2: bin valid points; first point of a voxel appends it to the occupied list ----
__global__ void __launch_bounds__(256)
bin_points_kernel(const float* __restrict__ xyz,
                  const unsigned int* __restrict__ mask)
{
    const int p = blockIdx.x * blockDim.x + threadIdx.x;
    if (p >= TOTAL) return;
    if (mask[p] == 0u) return;

    const float x = xyz[p * 3 + 0];
    const float y = xyz[p * 3 + 1];
    const float z = xyz[p * 3 + 2];
    const int ivx = (int)floorf(x / 0.32f) + 234;
    const int ivy = (int)floorf(y / 0.32f) + 234;
    const int ivz = (int)floorf(z / 6.0f) + 1;
    if (ivx < 0 || ivx >= GRID_X || ivy < 0 || ivy >= GRID_Y || ivz != 0) return;

    const int batch = p / NPTS;
    const int vid = batch * VOL + ivx * GRID_X + ivy;
    const int slot = atomicAdd(&d_cnt[vid], 1);
    if (slot < CAP) d_pidx[(size_t)vid * CAP + slot] = p;
    if (slot == 0) {
        const int li = atomicAdd(&d_nocc, 1);
        d_occ[li] = vid;
    }
}

// ---- K3: fill occupied voxels (runs after memset-to-zero of out) ----
__global__ void __launch_bounds__(FILL_THREADS, 2)
fill_kernel(const float* __restrict__ xyz,
            const float* __restrict__ pfeat,
            const float* __restrict__ W,
            const float* __restrict__ bias,
            float* __restrict__ out)
{
    const int lane   = threadIdx.x & 31;
    const int gwarp  = (blockIdx.x * FILL_THREADS + threadIdx.x) >> 5;
    const int nwarps = (FILL_BLOCKS * FILL_THREADS) >> 5;

    // Lane owns output columns 4L..4L+3; weights as packed f32x2 pairs.
    unsigned long long w01[D_TOT], w23[D_TOT];
    #pragma unroll
    for (int d = 0; d < D_TOT; ++d) {
        const float4 wr = ((const float4*)(W + d * MLP_N))[lane];
        w01[d] = pack2(wr.x, wr.y);
        w23[d] = pack2(wr.z, wr.w);
    }
    const float4 b4 = ((const float4*)bias)[lane];
    const unsigned long long b01 = pack2(b4.x, b4.y);
    const unsigned long long b23 = pack2(b4.z, b4.w);

    const int n = __ldg(&d_nocc);

    // Software pipeline: vid/cnt/first-pidx prefetched one iteration ahead.
    int idx = gwarp;
    int vid = 0, cnt = 0, p0 = 0;
    if (idx < n) {
        vid = __ldg(&d_occ[idx]);
        cnt = __ldg(&d_cnt[vid]);
        p0  = __ldg(&d_pidx[(size_t)vid * CAP]);
    }

    while (idx < n) {
        const int idx2 = idx + nwarps;
        int vid2 = 0, cnt2 = 0, p02 = 0;
        if (idx2 < n) {
            vid2 = __ldg(&d_occ[idx2]);
            cnt2 = __ldg(&d_cnt[vid2]);
            p02  = __ldg(&d_pidx[(size_t)vid2 * CAP]);
        }

        const int npt = cnt < CAP ? cnt : CAP;
        unsigned long long vmax01 = pack2(-1e30f, -1e30f);
        unsigned long long vmax23 = vmax01;

        for (int k = 0; k < npt; ++k) {
            const int p = (k == 0) ? p0 : __ldg(&d_pidx[(size_t)vid * CAP + k]);
            const float x = xyz[p * 3 + 0];
            const float y = xyz[p * 3 + 1];
            const float z = xyz[p * 3 + 2];
            const float dx = x - floorf(x / 0.32f) * 0.32f;
            const float dy = y - floorf(y / 0.32f) * 0.32f;
            const float dz = z - floorf(z / 6.0f) * 6.0f;

            const float4* f4 = (const float4*)(pfeat + (size_t)p * D_IN);
            const float4 fa = f4[0], fb = f4[1], fc = f4[2], fd = f4[3];
            const float vin[D_TOT] = {
                fa.x, fa.y, fa.z, fa.w,
                fb.x, fb.y, fb.z, fb.w,
                fc.x, fc.y, fc.z, fc.w,
                fd.x, fd.y, fd.z, fd.w,
                dx, dy, dz
            };
            unsigned long long acc01 = b01, acc23 = b23;
            #pragma unroll
            for (int d = 0; d < D_TOT; ++d) {
                const unsigned long long vv = dup2(vin[d]);
                acc01 = fma2(vv, w01[d], acc01);
                acc23 = fma2(vv, w23[d], acc23);
            }
            float a0, a1, a2, a3, m0, m1, m2, m3;
            unpack2(acc01, a0, a1); unpack2(acc23, a2, a3);
            unpack2(vmax01, m0, m1); unpack2(vmax23, m2, m3);
            vmax01 = pack2(fmaxf(m0, a0), fmaxf(m1, a1));
            vmax23 = pack2(fmaxf(m2, a2), fmaxf(m3, a3));
        }

        float m0, m1, m2, m3;
        unpack2(vmax01, m0, m1);
        unpack2(vmax23, m2, m3);
        // relu monotone: max-then-relu == max-of-relus; empty stays memset 0
        float4* dst = ((float4*)(out + (size_t)vid * MLP_N)) + lane;
        *dst = make_float4(fmaxf(m0, 0.f), fmaxf(m1, 0.f),
                           fmaxf(m2, 0.f), fmaxf(m3, 0.f));

        idx = idx2; vid = vid2; cnt = cnt2; p0 = p02;
    }
}

extern "C" void kernel_launch(void* const* d_in, const int* in_sizes, int n_in,
                              void* d_out, int out_size)
{
    const float*        xyz   = (const float*)d_in[0];
    const float*        pfeat = (const float*)d_in[1];
    const unsigned int* mask  = (const unsigned int*)d_in[2];
    const float*        W     = (const float*)d_in[3];
    const float*        bias  = (const float*)d_in[4];
    float*              out   = (float*)d_out;

    // Bulk zero of the dense grid at near-spec HBM bandwidth.
    cudaMemsetAsync(d_out, 0, (size_t)out_size * sizeof(float), 0);

    zero_cnt_kernel<<<(NVOX / 4 + 511) / 512, 512>>>();
    bin_points_kernel<<<(TOTAL + 255) / 256, 256>>>(xyz, mask);
    fill_kernel<<<FILL_BLOCKS, FILL_THREADS>>>(xyz, pfeat, W, bias, out);
}